// round 2
// baseline (speedup 1.0000x reference)
#include <cuda_runtime.h>
#include <math.h>

#define NN   10000
#define EE   320000
#define DIM  176
#define ATT  16
#define SHH  16
#define THH  4
#define NHH  20
#define VD   11
#define NSPH 16
#define RDIMC 16

typedef unsigned long long u64;

// ---------------- scratch (static device allocations) ----------------
__device__ float g_xi[NN * DIM];
__device__ float g_q [NN * NHH * ATT];
__device__ float g_k [NN * NHH * ATT];
__device__ float g_v [NN * DIM];
__device__ float g_mi[NN * DIM];
__device__ float g_Vi[NN * THH * NSPH];
__device__ float g_Y [EE * NSPH];
__device__ float g_rad[EE * RDIMC];
__device__ float g_G [NN * DIM];
__device__ float g_a [(long long)EE * NHH];
__device__ int   g_rowptr[NN + 1];
__device__ int   g_cnt[NN];
__device__ int   g_eid[EE];

// ---------------- helpers ----------------
__device__ __forceinline__ u64 pack2(float x, float y) {
    u64 r; asm("mov.b64 %0,{%1,%2};" : "=l"(r) : "f"(x), "f"(y)); return r;
}
__device__ __forceinline__ void fma2(u64& d, u64 a, u64 b) {
    asm("fma.rn.f32x2 %0, %1, %2, %3;" : "=l"(d) : "l"(a), "l"(b), "l"(d));
}
__device__ __forceinline__ float2 unpack2(u64 v) {
    float2 f; asm("mov.b64 {%0,%1},%2;" : "=f"(f.x), "=f"(f.y) : "l"(v)); return f;
}

// block reduction for blockDim=192 (6 warps)
__device__ __forceinline__ float block_sum_192(float v, float* red) {
    #pragma unroll
    for (int o = 16; o; o >>= 1) v += __shfl_xor_sync(0xffffffffu, v, o);
    if ((threadIdx.x & 31) == 0) red[threadIdx.x >> 5] = v;
    __syncthreads();
    float s = 0.f;
    if (threadIdx.x < 6) s = red[threadIdx.x];
    if (threadIdx.x < 32) {
        s += __shfl_xor_sync(0xffffffffu, s, 4);
        s += __shfl_xor_sync(0xffffffffu, s, 2);
        s += __shfl_xor_sync(0xffffffffu, s, 1);
        if (threadIdx.x == 0) red[0] = s;
    }
    __syncthreads();
    float r = red[0];
    __syncthreads();
    return r;
}

// ---------------- CSR build ----------------
__global__ void csr_zero_kernel() {
    int i = blockIdx.x * blockDim.x + threadIdx.x;
    if (i < NN) g_cnt[i] = 0;
}
__global__ void csr_count_kernel(const int* __restrict__ dst) {
    int e = blockIdx.x * blockDim.x + threadIdx.x;
    if (e < EE) atomicAdd(&g_cnt[dst[e]], 1);
}
__global__ __launch_bounds__(1024) void csr_scan_kernel() {
    __shared__ int s_warp[32];
    int tid = threadIdx.x;
    int lane = tid & 31, w = tid >> 5;
    int run = 0;
    for (int chunk = 0; chunk < NN; chunk += 1024) {
        int i = chunk + tid;
        int val = (i < NN) ? g_cnt[i] : 0;
        int v = val;
        #pragma unroll
        for (int o = 1; o < 32; o <<= 1) {
            int n = __shfl_up_sync(0xffffffffu, v, o);
            if (lane >= o) v += n;
        }
        if (lane == 31) s_warp[w] = v;
        __syncthreads();
        if (w == 0) {
            int x = s_warp[lane];
            #pragma unroll
            for (int o = 1; o < 32; o <<= 1) {
                int n = __shfl_up_sync(0xffffffffu, x, o);
                if (lane >= o) x += n;
            }
            s_warp[lane] = x;
        }
        __syncthreads();
        int incl = v + (w > 0 ? s_warp[w - 1] : 0);
        int excl = incl - val + run;
        if (i < NN) { g_rowptr[i] = excl; g_cnt[i] = excl; }
        run += s_warp[31];
        __syncthreads();
    }
    if (tid == 0) g_rowptr[NN] = run;
}
__global__ void csr_scatter_kernel(const int* __restrict__ dst) {
    int e = blockIdx.x * blockDim.x + threadIdx.x;
    if (e < EE) {
        int pos = atomicAdd(&g_cnt[dst[e]], 1);
        g_eid[pos] = e;
    }
}

// ---------------- node embedding ----------------
__global__ void node_embed_kernel(const int* __restrict__ species,
                                  const float* __restrict__ zt,
                                  const float* __restrict__ wsp) {
    __shared__ float sZ[16];
    __shared__ float red[8];
    int n = blockIdx.x;
    int t = threadIdx.x;
    if (t < 16) sZ[t] = zt[species[n] * 16 + t];
    __syncthreads();
    float val = 0.f;
    if (t < DIM) {
        #pragma unroll
        for (int z = 0; z < 16; z++) val += sZ[z] * wsp[z * DIM + t];
    }
    float mu = block_sum_192(val, red) * (1.f / DIM);
    float dx = (t < DIM) ? (val - mu) : 0.f;
    float var = block_sum_192(dx * dx, red) * (1.f / DIM);
    if (t < DIM) g_xi[n * DIM + t] = dx * rsqrtf(var + 1e-6f);
}

// ---------------- edge geometry ----------------
__global__ void edge_geom_kernel(const float* __restrict__ dist,
                                 const float* __restrict__ vec) {
    int e = blockIdx.x * blockDim.x + threadIdx.x;
    if (e >= EE) return;
    float d = dist[e];
    float inv = 1.f / d;
    float x = vec[e * 3 + 0] * inv;
    float y = vec[e * 3 + 1] * inv;
    float z = vec[e * 3 + 2] * inv;
    const float s3  = 1.7320508075688772f;
    const float s15 = 3.872983346207417f;
    const float c1  = 0.7905694150420949f;
    const float c2  = 0.6123724356957945f;
    float x2 = x * x, y2 = y * y, z2 = z * z;
    float Y[16];
    Y[0]  = 1.f;
    Y[1]  = x; Y[2] = y; Y[3] = z;
    Y[4]  = s3 * x * y;
    Y[5]  = s3 * y * z;
    Y[6]  = 0.5f * (3.f * z2 - 1.f);
    Y[7]  = s3 * x * z;
    Y[8]  = 0.5f * s3 * (x2 - y2);
    Y[9]  = c1 * y * (3.f * x2 - y2);
    Y[10] = s15 * x * y * z;
    Y[11] = c2 * y * (5.f * z2 - 1.f);
    Y[12] = 0.5f * z * (5.f * z2 - 3.f);
    Y[13] = c2 * x * (5.f * z2 - 1.f);
    Y[14] = 0.5f * s15 * z * (x2 - y2);
    Y[15] = c1 * x * (x2 - 3.f * y2);
    float R[16];
    const float sigma = 0.28f;
    const float invs = 1.f / 0.28f;
    #pragma unroll
    for (int r = 0; r < 16; r++) {
        float c = 0.8f + sigma * (float)r;
        float tt = (d - c) * invs;
        R[r] = expf(-tt * tt);
    }
    float4* yo = reinterpret_cast<float4*>(g_Y + e * 16);
    float4* ro = reinterpret_cast<float4*>(g_rad + e * 16);
    #pragma unroll
    for (int i = 0; i < 4; i++) {
        yo[i] = make_float4(Y[4*i], Y[4*i+1], Y[4*i+2], Y[4*i+3]);
        ro[i] = make_float4(R[4*i], R[4*i+1], R[4*i+2], R[4*i+3]);
    }
}

// ---------------- SGEMM with packed f32x2 FMA ----------------
__global__ __launch_bounds__(256) void sgemm_kernel(
    const float* __restrict__ A, const float* __restrict__ A2,
    int K1, int Ktot,
    const float* __restrict__ B, float* __restrict__ C,
    int M, int Ncols)
{
    __shared__ u64   As2[16][128];
    __shared__ float Bs [16][128];
    int tid = threadIdx.x;
    int tx = tid & 15, ty = tid >> 4;
    int row0 = blockIdx.y * 128;
    int col0 = blockIdx.x * 128;
    u64 acc[8][4];
    #pragma unroll
    for (int i = 0; i < 8; i++)
        #pragma unroll
        for (int j = 0; j < 4; j++) acc[i][j] = 0ull;

    int nk = Ktot / 16;
    for (int kt = 0; kt < nk; ++kt) {
        int gkbase = kt * 16;
        {
            int r  = tid >> 1;
            int c0 = (tid & 1) * 8;
            int grow = row0 + r;
            const float* Ap; int stride; int koff;
            if (gkbase < K1) { Ap = A;  stride = K1;        koff = gkbase; }
            else             { Ap = A2; stride = Ktot - K1; koff = gkbase - K1; }
            float4 v0 = make_float4(0,0,0,0), v1 = make_float4(0,0,0,0);
            if (grow < M) {
                const float* src = Ap + (long long)grow * stride + koff + c0;
                v0 = *reinterpret_cast<const float4*>(src);
                v1 = *reinterpret_cast<const float4*>(src + 4);
            }
            As2[c0+0][r] = pack2(v0.x, v0.x);
            As2[c0+1][r] = pack2(v0.y, v0.y);
            As2[c0+2][r] = pack2(v0.z, v0.z);
            As2[c0+3][r] = pack2(v0.w, v0.w);
            As2[c0+4][r] = pack2(v1.x, v1.x);
            As2[c0+5][r] = pack2(v1.y, v1.y);
            As2[c0+6][r] = pack2(v1.z, v1.z);
            As2[c0+7][r] = pack2(v1.w, v1.w);
        }
        {
            int br = tid >> 4;
            int bc = (tid & 15) * 8;
            int gk = gkbase + br;
            int gcol = col0 + bc;
            float4 v0 = make_float4(0,0,0,0), v1 = make_float4(0,0,0,0);
            if (gcol < Ncols) {
                const float* src = B + (long long)gk * Ncols + gcol;
                v0 = *reinterpret_cast<const float4*>(src);
                v1 = *reinterpret_cast<const float4*>(src + 4);
            }
            *reinterpret_cast<float4*>(&Bs[br][bc])     = v0;
            *reinterpret_cast<float4*>(&Bs[br][bc + 4]) = v1;
        }
        __syncthreads();
        #pragma unroll
        for (int k = 0; k < 16; ++k) {
            u64 a[8];
            {
                const ulonglong2* p = reinterpret_cast<const ulonglong2*>(&As2[k][ty * 8]);
                ulonglong2 q0 = p[0], q1 = p[1], q2 = p[2], q3 = p[3];
                a[0]=q0.x; a[1]=q0.y; a[2]=q1.x; a[3]=q1.y;
                a[4]=q2.x; a[5]=q2.y; a[6]=q3.x; a[7]=q3.y;
            }
            u64 b[4];
            {
                const ulonglong2* p = reinterpret_cast<const ulonglong2*>(&Bs[k][tx * 8]);
                ulonglong2 w0 = p[0], w1 = p[1];
                b[0]=w0.x; b[1]=w0.y; b[2]=w1.x; b[3]=w1.y;
            }
            #pragma unroll
            for (int i = 0; i < 8; i++)
                #pragma unroll
                for (int j = 0; j < 4; j++)
                    fma2(acc[i][j], a[i], b[j]);
        }
        __syncthreads();
    }
    #pragma unroll
    for (int i = 0; i < 8; i++) {
        int gr = row0 + ty * 8 + i;
        if (gr >= M) continue;
        #pragma unroll
        for (int j = 0; j < 4; j++) {
            int gc = col0 + tx * 8 + j * 2;
            if (gc < Ncols) {
                float2 f = unpack2(acc[i][j]);
                *reinterpret_cast<float2*>(&C[(long long)gr * Ncols + gc]) = f;
            }
        }
    }
}

// ---------------- phase 1: per-edge attention coefficients ----------------
template<int LAYER>
__global__ __launch_bounds__(256) void edge_coef_kernel(
    const int* __restrict__ src, const int* __restrict__ dst,
    const float* __restrict__ swtch,
    const float* __restrict__ pw1, const float* __restrict__ pb1,
    const float* __restrict__ pw2, const float* __restrict__ pb2)
{
    constexpr int UR = (LAYER == 0) ? 16 : 32;
    __shared__ float s_pw1[UR * 32];
    __shared__ float s_pw2[32 * 16];
    __shared__ float s_b1[32];
    __shared__ float s_b2[16];
    __shared__ float s_ur[8][32];
    __shared__ float s_Y[8][16];
    __shared__ float s_a[8][20];

    int tid = threadIdx.x;
    for (int i = tid; i < UR * 32; i += 256) s_pw1[i] = pw1[i];
    for (int i = tid; i < 512;     i += 256) s_pw2[i] = pw2[i];
    if (tid < 32) s_b1[tid] = pb1[tid];
    if (tid < 16) s_b2[tid] = pb2[tid];
    __syncthreads();

    int wid = tid >> 5, lane = tid & 31;
    int e = blockIdx.x * 8 + wid;
    if (e >= EE) return;
    int is = src[e], id = dst[e];
    if (lane < 16) {
        s_ur[wid][lane] = g_rad[e * 16 + lane];
        s_Y [wid][lane] = g_Y  [e * 16 + lane];
    }
    __syncwarp();
    if (LAYER == 1) {
        if (lane < 4) {
            const float* Vd = &g_Vi[id * 64 + lane * 16];
            const float* Vs = &g_Vi[is * 64 + lane * 16];
            float u0 = (Vd[0] + Vs[0]) * s_Y[wid][0];
            float u1 = 0.f, u2 = 0.f, u3 = 0.f;
            #pragma unroll
            for (int m = 1; m < 4; m++)  u1 += (Vd[m] - Vs[m]) * s_Y[wid][m];
            #pragma unroll
            for (int m = 4; m < 9; m++)  u2 += (Vd[m] + Vs[m]) * s_Y[wid][m];
            #pragma unroll
            for (int m = 9; m < 16; m++) u3 += (Vd[m] - Vs[m]) * s_Y[wid][m];
            s_ur[wid][16 + lane] = u0;
            s_ur[wid][20 + lane] = u1;
            s_ur[wid][24 + lane] = u2;
            s_ur[wid][28 + lane] = u3;
        }
        __syncwarp();
    }
    // MLP hidden (32 units, one per lane)
    float h = s_b1[lane];
    #pragma unroll
    for (int r = 0; r < UR; r++) h += s_ur[wid][r] * s_pw1[r * 32 + lane];
    h = h / (1.f + expf(-h));   // swish
    int dl = lane & 15;
    float wv = s_b2[dl];
    #pragma unroll
    for (int j = 0; j < 32; j++)
        wv += __shfl_sync(0xffffffffu, h, j) * s_pw2[j * 16 + dl];
    float sws = swtch[e] * 0.25f;
    const float* qr = &g_q[id * 320];
    const float* kr = &g_k[is * 320];
    int hh = lane >> 4;
    #pragma unroll
    for (int p = 0; p < 10; p++) {
        int hd = (p * 2 + hh) * 16 + dl;
        float pr = qr[hd] * kr[hd] * wv;
        pr += __shfl_xor_sync(0xffffffffu, pr, 1, 16);
        pr += __shfl_xor_sync(0xffffffffu, pr, 2, 16);
        pr += __shfl_xor_sync(0xffffffffu, pr, 4, 16);
        pr += __shfl_xor_sync(0xffffffffu, pr, 8, 16);
        if (dl == 0) s_a[wid][p * 2 + hh] = pr * sws;
    }
    __syncwarp();
    if (lane < 20) g_a[(long long)e * 20 + lane] = s_a[wid][lane];
}

// ---------------- phase 2: per-node gather-aggregate (no atomics) ----------------
template<int LAYER>
__global__ __launch_bounds__(256) void node_aggr_kernel(const int* __restrict__ src)
{
    __shared__ int   s_src[8];
    __shared__ float s_a[8][20];
    __shared__ float s_Y[8][16];

    int n = blockIdx.x;
    int t = threadIdx.x;
    int begin = g_rowptr[n], end = g_rowptr[n + 1];
    float acc = 0.f;
    int hidx = (t < DIM) ? (t / VD) : 0;          // shared head for mi
    int j = t - DIM;                               // Vi component (0..63)
    for (int base = begin; base < end; base += 8) {
        int cnt = min(8, end - base);
        for (int i = t; i < cnt * 20; i += 256) {
            int e = i / 20, c = i - e * 20;
            s_a[e][c] = g_a[(long long)g_eid[base + e] * 20 + c];
        }
        if (LAYER == 0) {
            for (int i = t; i < cnt * 16; i += 256) {
                int e = i >> 4;
                s_Y[e][i & 15] = g_Y[g_eid[base + e] * 16 + (i & 15)];
            }
        }
        if (t < cnt) s_src[t] = src[g_eid[base + t]];
        __syncthreads();
        if (t < DIM) {
            for (int i = 0; i < cnt; i++)
                acc += s_a[i][hidx] * g_v[(long long)s_src[i] * DIM + t];
        } else if (LAYER == 0 && j < 64) {
            for (int i = 0; i < cnt; i++)
                acc += s_a[i][16 + (j >> 4)] * s_Y[i][j & 15];
        }
        __syncthreads();
    }
    if (t < DIM) g_mi[(long long)n * DIM + t] = acc;
    else if (LAYER == 0 && j < 64) g_Vi[n * 64 + j] = acc;
}

// ---------------- residual + LayerNorm ----------------
__global__ void resln_kernel(const float* __restrict__ ub, float* __restrict__ out, int toXi) {
    __shared__ float red[8];
    int n = blockIdx.x, t = threadIdx.x;
    float val = 0.f;
    if (t < DIM) val = g_xi[n * DIM + t] + g_G[n * DIM + t] + ub[t];
    float mu = block_sum_192(val, red) * (1.f / DIM);
    float dx = (t < DIM) ? (val - mu) : 0.f;
    float var = block_sum_192(dx * dx, red) * (1.f / DIM);
    if (t < DIM) {
        float o = dx * rsqrtf(var + 1e-6f);
        if (toXi) g_xi[n * DIM + t] = o;
        else      out[n * DIM + t] = o;
    }
}

// ---------------- launch ----------------
static inline dim3 gemm_grid(int M, int Ncols) {
    return dim3((Ncols + 127) / 128, (M + 127) / 128);
}

extern "C" void kernel_launch(void* const* d_in, const int* in_sizes, int n_in,
                              void* d_out, int out_size) {
    const int*   species  = (const int*)  d_in[0];
    const float* dist     = (const float*)d_in[1];
    const float* swtch    = (const float*)d_in[2];
    const int*   esrc     = (const int*)  d_in[3];
    const int*   edst     = (const int*)  d_in[4];
    const float* vec      = (const float*)d_in[5];
    const float* z_table  = (const float*)d_in[6];
    const float* w_sp     = (const float*)d_in[7];
    const float* pw1_0    = (const float*)d_in[8];
    const float* pb1_0    = (const float*)d_in[9];
    const float* pw2_0    = (const float*)d_in[10];
    const float* pb2_0    = (const float*)d_in[11];
    const float* wq_0     = (const float*)d_in[12];
    const float* wk_0     = (const float*)d_in[13];
    const float* wv_0     = (const float*)d_in[14];
    const float* uw_0     = (const float*)d_in[15];
    const float* ub_0     = (const float*)d_in[16];
    const float* pw1_1    = (const float*)d_in[17];
    const float* pb1_1    = (const float*)d_in[18];
    const float* pw2_1    = (const float*)d_in[19];
    const float* pb2_1    = (const float*)d_in[20];
    const float* wq_1     = (const float*)d_in[21];
    const float* wk_1     = (const float*)d_in[22];
    const float* wv_1     = (const float*)d_in[23];
    const float* uw_1     = (const float*)d_in[24];
    const float* ub_1     = (const float*)d_in[25];
    float* out = (float*)d_out;

    float *gq, *gk, *gv, *gG, *gxi, *gmi;
    cudaGetSymbolAddress((void**)&gq, g_q);
    cudaGetSymbolAddress((void**)&gk, g_k);
    cudaGetSymbolAddress((void**)&gv, g_v);
    cudaGetSymbolAddress((void**)&gG, g_G);
    cudaGetSymbolAddress((void**)&gxi, g_xi);
    cudaGetSymbolAddress((void**)&gmi, g_mi);

    const int EB = (EE + 255) / 256;
    const int EWB = (EE + 7) / 8;     // warp-per-edge blocks

    // prologue: embedding, geometry, CSR build
    node_embed_kernel<<<NN, 192>>>(species, z_table, w_sp);
    edge_geom_kernel<<<EB, 256>>>(dist, vec);
    csr_zero_kernel<<<(NN + 255) / 256, 256>>>();
    csr_count_kernel<<<EB, 256>>>(edst);
    csr_scan_kernel<<<1, 1024>>>();
    csr_scatter_kernel<<<EB, 256>>>(edst);

    // ---- layer 0 ----
    sgemm_kernel<<<gemm_grid(NN, NHH * ATT), 256>>>(gxi, gxi, DIM, DIM, wq_0, gq, NN, NHH * ATT);
    sgemm_kernel<<<gemm_grid(NN, NHH * ATT), 256>>>(gxi, gxi, DIM, DIM, wk_0, gk, NN, NHH * ATT);
    sgemm_kernel<<<gemm_grid(NN, DIM), 256>>>(gxi, gxi, DIM, DIM, wv_0, gv, NN, DIM);
    edge_coef_kernel<0><<<EWB, 256>>>(esrc, edst, swtch, pw1_0, pb1_0, pw2_0, pb2_0);
    node_aggr_kernel<0><<<NN, 256>>>(esrc);
    sgemm_kernel<<<gemm_grid(NN, DIM), 256>>>(gxi, gmi, DIM, 2 * DIM, uw_0, gG, NN, DIM);
    resln_kernel<<<NN, 192>>>(ub_0, out, 1);

    // ---- layer 1 ----
    sgemm_kernel<<<gemm_grid(NN, NHH * ATT), 256>>>(gxi, gxi, DIM, DIM, wq_1, gq, NN, NHH * ATT);
    sgemm_kernel<<<gemm_grid(NN, NHH * ATT), 256>>>(gxi, gxi, DIM, DIM, wk_1, gk, NN, NHH * ATT);
    sgemm_kernel<<<gemm_grid(NN, DIM), 256>>>(gxi, gxi, DIM, DIM, wv_1, gv, NN, DIM);
    edge_coef_kernel<1><<<EWB, 256>>>(esrc, edst, swtch, pw1_1, pb1_1, pw2_1, pb2_1);
    node_aggr_kernel<1><<<NN, 256>>>(esrc);
    sgemm_kernel<<<gemm_grid(NN, DIM), 256>>>(gxi, gmi, DIM, 2 * DIM, uw_1, gG, NN, DIM);
    resln_kernel<<<NN, 192>>>(ub_1, out, 0);
}

// round 3
// speedup vs baseline: 1.2000x; 1.2000x over previous
#include <cuda_runtime.h>
#include <math.h>

#define NN   10000
#define EE   320000
#define DIM  176
#define ATT  16
#define SHH  16
#define THH  4
#define NHH  20
#define VD   11
#define NSPH 16
#define RDIMC 16
#define QKVW 816   // 320 + 320 + 176

typedef unsigned long long u64;

// ---------------- scratch ----------------
__device__ float g_xi [NN * DIM];
__device__ float g_qkv[NN * QKVW];
__device__ float g_mi [NN * DIM];
__device__ float g_Vi [NN * THH * NSPH];
__device__ float g_Y  [EE * NSPH];
__device__ float g_rad[EE * RDIMC];
__device__ float g_G  [NN * DIM];
__device__ float g_B  [DIM * QKVW];

// ---------------- helpers ----------------
__device__ __forceinline__ u64 pack2(float x, float y) {
    u64 r; asm("mov.b64 %0,{%1,%2};" : "=l"(r) : "f"(x), "f"(y)); return r;
}
__device__ __forceinline__ void fma2(u64& d, u64 a, u64 b) {
    asm("fma.rn.f32x2 %0, %1, %2, %3;" : "=l"(d) : "l"(a), "l"(b), "l"(d));
}
__device__ __forceinline__ float2 unpack2(u64 v) {
    float2 f; asm("mov.b64 {%0,%1},%2;" : "=f"(f.x), "=f"(f.y) : "l"(v)); return f;
}

__device__ __forceinline__ float block_sum_192(float v, float* red) {
    #pragma unroll
    for (int o = 16; o; o >>= 1) v += __shfl_xor_sync(0xffffffffu, v, o);
    if ((threadIdx.x & 31) == 0) red[threadIdx.x >> 5] = v;
    __syncthreads();
    float s = 0.f;
    if (threadIdx.x < 6) s = red[threadIdx.x];
    if (threadIdx.x < 32) {
        s += __shfl_xor_sync(0xffffffffu, s, 4);
        s += __shfl_xor_sync(0xffffffffu, s, 2);
        s += __shfl_xor_sync(0xffffffffu, s, 1);
        if (threadIdx.x == 0) red[0] = s;
    }
    __syncthreads();
    float r = red[0];
    __syncthreads();
    return r;
}

// ---------------- node embedding ----------------
__global__ void node_embed_kernel(const int* __restrict__ species,
                                  const float* __restrict__ zt,
                                  const float* __restrict__ wsp) {
    __shared__ float sZ[16];
    __shared__ float red[8];
    int n = blockIdx.x;
    int t = threadIdx.x;
    if (t < 16) sZ[t] = zt[species[n] * 16 + t];
    __syncthreads();
    float val = 0.f;
    if (t < DIM) {
        #pragma unroll
        for (int z = 0; z < 16; z++) val += sZ[z] * wsp[z * DIM + t];
    }
    float mu = block_sum_192(val, red) * (1.f / DIM);
    float dx = (t < DIM) ? (val - mu) : 0.f;
    float var = block_sum_192(dx * dx, red) * (1.f / DIM);
    if (t < DIM) g_xi[n * DIM + t] = dx * rsqrtf(var + 1e-6f);
}

// ---------------- edge geometry ----------------
__global__ void edge_geom_kernel(const float* __restrict__ dist,
                                 const float* __restrict__ vec) {
    int e = blockIdx.x * blockDim.x + threadIdx.x;
    if (e >= EE) return;
    float d = dist[e];
    float inv = 1.f / d;
    float x = vec[e * 3 + 0] * inv;
    float y = vec[e * 3 + 1] * inv;
    float z = vec[e * 3 + 2] * inv;
    const float s3  = 1.7320508075688772f;
    const float s15 = 3.872983346207417f;
    const float c1  = 0.7905694150420949f;
    const float c2  = 0.6123724356957945f;
    float x2 = x * x, y2 = y * y, z2 = z * z;
    float Y[16];
    Y[0]  = 1.f;
    Y[1]  = x; Y[2] = y; Y[3] = z;
    Y[4]  = s3 * x * y;
    Y[5]  = s3 * y * z;
    Y[6]  = 0.5f * (3.f * z2 - 1.f);
    Y[7]  = s3 * x * z;
    Y[8]  = 0.5f * s3 * (x2 - y2);
    Y[9]  = c1 * y * (3.f * x2 - y2);
    Y[10] = s15 * x * y * z;
    Y[11] = c2 * y * (5.f * z2 - 1.f);
    Y[12] = 0.5f * z * (5.f * z2 - 3.f);
    Y[13] = c2 * x * (5.f * z2 - 1.f);
    Y[14] = 0.5f * s15 * z * (x2 - y2);
    Y[15] = c1 * x * (x2 - 3.f * y2);
    float R[16];
    const float sigma = 0.28f;
    const float invs = 1.f / 0.28f;
    #pragma unroll
    for (int r = 0; r < 16; r++) {
        float c = 0.8f + sigma * (float)r;
        float tt = (d - c) * invs;
        R[r] = expf(-tt * tt);
    }
    float4* yo = reinterpret_cast<float4*>(g_Y + e * 16);
    float4* ro = reinterpret_cast<float4*>(g_rad + e * 16);
    #pragma unroll
    for (int i = 0; i < 4; i++) {
        yo[i] = make_float4(Y[4*i], Y[4*i+1], Y[4*i+2], Y[4*i+3]);
        ro[i] = make_float4(R[4*i], R[4*i+1], R[4*i+2], R[4*i+3]);
    }
}

// ---------------- build concatenated B = [wq | wk | wv] ----------------
__global__ void build_B_kernel(const float* __restrict__ wq,
                               const float* __restrict__ wk,
                               const float* __restrict__ wv) {
    int i = blockIdx.x * blockDim.x + threadIdx.x;
    if (i >= DIM * QKVW) return;
    int r = i / QKVW, c = i - r * QKVW;
    float v;
    if (c < 320)      v = wq[r * 320 + c];
    else if (c < 640) v = wk[r * 320 + (c - 320)];
    else              v = wv[r * 176 + (c - 640)];
    g_B[i] = v;
}

// ---------------- zero scratch ----------------
__global__ void zero_kernel(int doVi) {
    int i = blockIdx.x * blockDim.x + threadIdx.x;
    if (i < NN * DIM) g_mi[i] = 0.f;
    if (doVi && i < NN * THH * NSPH) g_Vi[i] = 0.f;
}

// ---------------- SGEMM with packed f32x2 FMA ----------------
__global__ __launch_bounds__(256) void sgemm_kernel(
    const float* __restrict__ A, const float* __restrict__ A2,
    int K1, int Ktot,
    const float* __restrict__ B, float* __restrict__ C,
    int M, int Ncols)
{
    __shared__ u64   As2[16][128];
    __shared__ float Bs [16][128];
    int tid = threadIdx.x;
    int tx = tid & 15, ty = tid >> 4;
    int row0 = blockIdx.y * 128;
    int col0 = blockIdx.x * 128;
    u64 acc[8][4];
    #pragma unroll
    for (int i = 0; i < 8; i++)
        #pragma unroll
        for (int j = 0; j < 4; j++) acc[i][j] = 0ull;

    int nk = Ktot / 16;
    for (int kt = 0; kt < nk; ++kt) {
        int gkbase = kt * 16;
        {
            int r  = tid >> 1;
            int c0 = (tid & 1) * 8;
            int grow = row0 + r;
            const float* Ap; int stride; int koff;
            if (gkbase < K1) { Ap = A;  stride = K1;        koff = gkbase; }
            else             { Ap = A2; stride = Ktot - K1; koff = gkbase - K1; }
            float4 v0 = make_float4(0,0,0,0), v1 = make_float4(0,0,0,0);
            if (grow < M) {
                const float* src = Ap + (long long)grow * stride + koff + c0;
                v0 = *reinterpret_cast<const float4*>(src);
                v1 = *reinterpret_cast<const float4*>(src + 4);
            }
            As2[c0+0][r] = pack2(v0.x, v0.x);
            As2[c0+1][r] = pack2(v0.y, v0.y);
            As2[c0+2][r] = pack2(v0.z, v0.z);
            As2[c0+3][r] = pack2(v0.w, v0.w);
            As2[c0+4][r] = pack2(v1.x, v1.x);
            As2[c0+5][r] = pack2(v1.y, v1.y);
            As2[c0+6][r] = pack2(v1.z, v1.z);
            As2[c0+7][r] = pack2(v1.w, v1.w);
        }
        {
            int br = tid >> 4;
            int bc = (tid & 15) * 8;
            int gk = gkbase + br;
            int gcol = col0 + bc;
            float4 v0 = make_float4(0,0,0,0), v1 = make_float4(0,0,0,0);
            if (gcol < Ncols) {
                const float* src = B + (long long)gk * Ncols + gcol;
                v0 = *reinterpret_cast<const float4*>(src);
                v1 = *reinterpret_cast<const float4*>(src + 4);
            }
            *reinterpret_cast<float4*>(&Bs[br][bc])     = v0;
            *reinterpret_cast<float4*>(&Bs[br][bc + 4]) = v1;
        }
        __syncthreads();
        #pragma unroll
        for (int k = 0; k < 16; ++k) {
            u64 a[8];
            {
                const ulonglong2* p = reinterpret_cast<const ulonglong2*>(&As2[k][ty * 8]);
                ulonglong2 q0 = p[0], q1 = p[1], q2 = p[2], q3 = p[3];
                a[0]=q0.x; a[1]=q0.y; a[2]=q1.x; a[3]=q1.y;
                a[4]=q2.x; a[5]=q2.y; a[6]=q3.x; a[7]=q3.y;
            }
            u64 b[4];
            {
                const ulonglong2* p = reinterpret_cast<const ulonglong2*>(&Bs[k][tx * 8]);
                ulonglong2 w0 = p[0], w1 = p[1];
                b[0]=w0.x; b[1]=w0.y; b[2]=w1.x; b[3]=w1.y;
            }
            #pragma unroll
            for (int i = 0; i < 8; i++)
                #pragma unroll
                for (int j = 0; j < 4; j++)
                    fma2(acc[i][j], a[i], b[j]);
        }
        __syncthreads();
    }
    #pragma unroll
    for (int i = 0; i < 8; i++) {
        int gr = row0 + ty * 8 + i;
        if (gr >= M) continue;
        #pragma unroll
        for (int j = 0; j < 4; j++) {
            int gc = col0 + tx * 8 + j * 2;
            if (gc < Ncols) {
                float2 f = unpack2(acc[i][j]);
                *reinterpret_cast<float2*>(&C[(long long)gr * Ncols + gc]) = f;
            }
        }
    }
}

// ---------------- edge attention + scatter (warp per edge, vectorized) ----------------
template<int LAYER>
__global__ __launch_bounds__(256) void edge_attn_kernel(
    const int* __restrict__ src, const int* __restrict__ dst,
    const float* __restrict__ swtch,
    const float* __restrict__ pw1, const float* __restrict__ pb1,
    const float* __restrict__ pw2, const float* __restrict__ pb2)
{
    constexpr int UR = (LAYER == 0) ? 16 : 32;
    __shared__ float s_pw1[UR * 32];
    __shared__ float s_pw2[32 * 16];
    __shared__ float s_b1[32];
    __shared__ float s_b2[16];
    __shared__ float s_ur[8][32];
    __shared__ float s_Y[8][16];
    __shared__ float s_w[8][16];
    __shared__ float s_a[8][20];

    int tid = threadIdx.x;
    for (int i = tid; i < UR * 32; i += 256) s_pw1[i] = pw1[i];
    for (int i = tid; i < 512;     i += 256) s_pw2[i] = pw2[i];
    if (tid < 32) s_b1[tid] = pb1[tid];
    if (tid < 16) s_b2[tid] = pb2[tid];
    __syncthreads();

    int wid = tid >> 5, lane = tid & 31;
    int e = blockIdx.x * 8 + wid;
    if (e >= EE) return;
    int is = src[e], id = dst[e];
    if (lane < 16) {
        s_ur[wid][lane] = g_rad[e * 16 + lane];
        s_Y [wid][lane] = g_Y  [e * 16 + lane];
    }
    __syncwarp();
    if (LAYER == 1) {
        if (lane < 4) {
            const float4* Vd4 = reinterpret_cast<const float4*>(&g_Vi[id * 64 + lane * 16]);
            const float4* Vs4 = reinterpret_cast<const float4*>(&g_Vi[is * 64 + lane * 16]);
            float Vd[16], Vs[16];
            #pragma unroll
            for (int i = 0; i < 4; i++) {
                float4 a4 = Vd4[i], b4 = Vs4[i];
                Vd[4*i]=a4.x; Vd[4*i+1]=a4.y; Vd[4*i+2]=a4.z; Vd[4*i+3]=a4.w;
                Vs[4*i]=b4.x; Vs[4*i+1]=b4.y; Vs[4*i+2]=b4.z; Vs[4*i+3]=b4.w;
            }
            float u0 = (Vd[0] + Vs[0]) * s_Y[wid][0];
            float u1 = 0.f, u2 = 0.f, u3 = 0.f;
            #pragma unroll
            for (int m = 1; m < 4; m++)  u1 += (Vd[m] - Vs[m]) * s_Y[wid][m];
            #pragma unroll
            for (int m = 4; m < 9; m++)  u2 += (Vd[m] + Vs[m]) * s_Y[wid][m];
            #pragma unroll
            for (int m = 9; m < 16; m++) u3 += (Vd[m] - Vs[m]) * s_Y[wid][m];
            s_ur[wid][16 + lane] = u0;
            s_ur[wid][20 + lane] = u1;
            s_ur[wid][24 + lane] = u2;
            s_ur[wid][28 + lane] = u3;
        }
        __syncwarp();
    }
    // MLP hidden: 32 units, one per lane
    float h = s_b1[lane];
    #pragma unroll
    for (int r = 0; r < UR; r++) h += s_ur[wid][r] * s_pw1[r * 32 + lane];
    h = h / (1.f + expf(-h));   // swish
    // second layer: lanes hold w[lane&15]; lanes<16 publish to smem
    int dl = lane & 15;
    float wv = s_b2[dl];
    #pragma unroll
    for (int j = 0; j < 32; j++)
        wv += __shfl_sync(0xffffffffu, h, j) * s_pw2[j * 16 + dl];
    if (lane < 16) s_w[wid][lane] = wv;
    __syncwarp();
    // logits: one head per lane (20 lanes), vector loads
    float sws = swtch[e] * 0.25f;
    const float* qr = g_qkv + (long long)id * QKVW;          // q at offset 0
    const float* kr = g_qkv + (long long)is * QKVW + 320;    // k at offset 320
    if (lane < 20) {
        float acc = 0.f;
        #pragma unroll
        for (int i = 0; i < 4; i++) {
            float4 q4 = *reinterpret_cast<const float4*>(qr + lane * 16 + i * 4);
            float4 k4 = *reinterpret_cast<const float4*>(kr + lane * 16 + i * 4);
            float4 w4 = *reinterpret_cast<const float4*>(&s_w[wid][i * 4]);
            acc += q4.x * k4.x * w4.x;
            acc += q4.y * k4.y * w4.y;
            acc += q4.z * k4.z * w4.z;
            acc += q4.w * k4.w * w4.w;
        }
        s_a[wid][lane] = acc * sws;
    }
    __syncwarp();
    // scatter mi += a_s[h] * v[src]  (float4 atomics)
    const float* vr = g_qkv + (long long)is * QKVW + 640;    // v at offset 640
    float* mr = &g_mi[(long long)id * DIM];
    #pragma unroll
    for (int t4 = lane; t4 < 44; t4 += 32) {
        int b0 = 4 * t4;
        float4 v4 = *reinterpret_cast<const float4*>(vr + b0);
        float4 out;
        out.x = s_a[wid][ b0      / VD] * v4.x;
        out.y = s_a[wid][(b0 + 1) / VD] * v4.y;
        out.z = s_a[wid][(b0 + 2) / VD] * v4.z;
        out.w = s_a[wid][(b0 + 3) / VD] * v4.w;
        atomicAdd(reinterpret_cast<float4*>(mr + b0), out);
    }
    // scatter Vi += a_t * Y  (layer 0 only; Vi_old == 0)
    if (LAYER == 0) {
        if (lane < 16) {
            int j0 = 4 * lane;
            float at = s_a[wid][16 + (lane >> 2)];
            float4 y4 = *reinterpret_cast<const float4*>(&s_Y[wid][4 * (lane & 3)]);
            float4 out = make_float4(at * y4.x, at * y4.y, at * y4.z, at * y4.w);
            atomicAdd(reinterpret_cast<float4*>(&g_Vi[(long long)id * 64 + j0]), out);
        }
    }
}

// ---------------- residual + LayerNorm ----------------
__global__ void resln_kernel(const float* __restrict__ ub, float* __restrict__ out, int toXi) {
    __shared__ float red[8];
    int n = blockIdx.x, t = threadIdx.x;
    float val = 0.f;
    if (t < DIM) val = g_xi[n * DIM + t] + g_G[n * DIM + t] + ub[t];
    float mu = block_sum_192(val, red) * (1.f / DIM);
    float dx = (t < DIM) ? (val - mu) : 0.f;
    float var = block_sum_192(dx * dx, red) * (1.f / DIM);
    if (t < DIM) {
        float o = dx * rsqrtf(var + 1e-6f);
        if (toXi) g_xi[n * DIM + t] = o;
        else      out[n * DIM + t] = o;
    }
}

// ---------------- launch ----------------
static inline dim3 gemm_grid(int M, int Ncols) {
    return dim3((Ncols + 127) / 128, (M + 127) / 128);
}

extern "C" void kernel_launch(void* const* d_in, const int* in_sizes, int n_in,
                              void* d_out, int out_size) {
    const int*   species  = (const int*)  d_in[0];
    const float* dist     = (const float*)d_in[1];
    const float* swtch    = (const float*)d_in[2];
    const int*   esrc     = (const int*)  d_in[3];
    const int*   edst     = (const int*)  d_in[4];
    const float* vec      = (const float*)d_in[5];
    const float* z_table  = (const float*)d_in[6];
    const float* w_sp     = (const float*)d_in[7];
    const float* pw1_0    = (const float*)d_in[8];
    const float* pb1_0    = (const float*)d_in[9];
    const float* pw2_0    = (const float*)d_in[10];
    const float* pb2_0    = (const float*)d_in[11];
    const float* wq_0     = (const float*)d_in[12];
    const float* wk_0     = (const float*)d_in[13];
    const float* wv_0     = (const float*)d_in[14];
    const float* uw_0     = (const float*)d_in[15];
    const float* ub_0     = (const float*)d_in[16];
    const float* pw1_1    = (const float*)d_in[17];
    const float* pb1_1    = (const float*)d_in[18];
    const float* pw2_1    = (const float*)d_in[19];
    const float* pb2_1    = (const float*)d_in[20];
    const float* wq_1     = (const float*)d_in[21];
    const float* wk_1     = (const float*)d_in[22];
    const float* wv_1     = (const float*)d_in[23];
    const float* uw_1     = (const float*)d_in[24];
    const float* ub_1     = (const float*)d_in[25];
    float* out = (float*)d_out;

    float *gqkv, *gG, *gxi, *gmi, *gB;
    cudaGetSymbolAddress((void**)&gqkv, g_qkv);
    cudaGetSymbolAddress((void**)&gG, g_G);
    cudaGetSymbolAddress((void**)&gxi, g_xi);
    cudaGetSymbolAddress((void**)&gmi, g_mi);
    cudaGetSymbolAddress((void**)&gB, g_B);

    const int EB  = (EE + 255) / 256;
    const int EWB = (EE + 7) / 8;
    const int ZGRID = (NN * DIM + 255) / 256;
    const int BGRID = (DIM * QKVW + 255) / 256;

    node_embed_kernel<<<NN, 192>>>(species, z_table, w_sp);
    edge_geom_kernel<<<EB, 256>>>(dist, vec);

    // ---- layer 0 ----
    build_B_kernel<<<BGRID, 256>>>(wq_0, wk_0, wv_0);
    sgemm_kernel<<<gemm_grid(NN, QKVW), 256>>>(gxi, gxi, DIM, DIM, gB, gqkv, NN, QKVW);
    zero_kernel<<<ZGRID, 256>>>(1);
    edge_attn_kernel<0><<<EWB, 256>>>(esrc, edst, swtch, pw1_0, pb1_0, pw2_0, pb2_0);
    sgemm_kernel<<<gemm_grid(NN, DIM), 256>>>(gxi, gmi, DIM, 2 * DIM, uw_0, gG, NN, DIM);
    resln_kernel<<<NN, 192>>>(ub_0, out, 1);

    // ---- layer 1 ----
    build_B_kernel<<<BGRID, 256>>>(wq_1, wk_1, wv_1);
    sgemm_kernel<<<gemm_grid(NN, QKVW), 256>>>(gxi, gxi, DIM, DIM, gB, gqkv, NN, QKVW);
    zero_kernel<<<ZGRID, 256>>>(0);
    edge_attn_kernel<1><<<EWB, 256>>>(esrc, edst, swtch, pw1_1, pb1_1, pw2_1, pb2_1);
    sgemm_kernel<<<gemm_grid(NN, DIM), 256>>>(gxi, gmi, DIM, 2 * DIM, uw_1, gG, NN, DIM);
    resln_kernel<<<NN, 192>>>(ub_1, out, 0);
}